// round 14
// baseline (speedup 1.0000x reference)
#include <cuda_runtime.h>
#include <cuda_fp16.h>
#include <math.h>
#include <stdint.h>

#define N_NODES 4096
#define N_EDGES 16384
#define D       64
#define BG      16
#define SLOPE   0.01f

#define NCH     16              // f-chunks: 4 f x 64 k each
#define SRCB    32              // src nodes per fused block
#define ECAP    320             // edge capacity per block (mean 128, 17 sigma)

// ---------------- device scratch ----------------
__device__ __half g_We2FT[4160 * D];      // [c][d]; c=f*64+k (c<4096), 4096+f = bias rows
__device__ __half g_he_h[N_EDGES * D];
__device__ __half g_he_p[N_EDGES * D];    // src-grouped permuted he
__device__ int2  g_sd_p[N_EDGES];         // (src,dst) per grouped slot
__device__ __half g_h_h[N_NODES * D];
__device__ float g_h[N_NODES * D];
__device__ float g_agg[N_NODES * D];
__device__ float g_deg[N_NODES];
__device__ float g_Wi4[D * D * 4];
__device__ float g_Wh4[D * D * 4];
__device__ float g_q[D];
__device__ float g_e[N_NODES];
__device__ float g_a[N_NODES];
__device__ float g_emax[BG];
__device__ float g_asum[BG];
__device__ float g_rpool[BG * D];
__device__ int g_scnt[N_NODES];
__device__ int g_rowptr[N_NODES + 1];
__device__ int g_fill[N_NODES];

__device__ __forceinline__ float lrelu(float x) { return x >= 0.f ? x : SLOPE * x; }
__device__ __forceinline__ float sigm(float x)  { return 1.f / (1.f + expf(-x)); }

__device__ __forceinline__ void atomicMaxF(float* addr, float v) {
    int* ai = (int*)addr;
    int old = *ai;
    while (__int_as_float(old) < v) {
        int assumed = old;
        old = atomicCAS(ai, assumed, __float_as_int(v));
        if (old == assumed) break;
    }
}

__device__ __forceinline__ void mma16816(float c[4],
                                         uint32_t a0, uint32_t a1, uint32_t a2, uint32_t a3,
                                         uint32_t b0, uint32_t b1) {
    asm volatile(
        "mma.sync.aligned.m16n8k16.row.col.f32.f16.f16.f32 "
        "{%0,%1,%2,%3}, {%4,%5,%6,%7}, {%8,%9}, {%0,%1,%2,%3};"
        : "+f"(c[0]), "+f"(c[1]), "+f"(c[2]), "+f"(c[3])
        : "r"(a0), "r"(a1), "r"(a2), "r"(a3), "r"(b0), "r"(b1));
}

__device__ __forceinline__ void ldsm_x4(uint32_t& r0, uint32_t& r1,
                                        uint32_t& r2, uint32_t& r3,
                                        const void* smem_ptr) {
    uint32_t addr;
    asm("{ .reg .u64 t; cvta.to.shared.u64 t, %1; cvt.u32.u64 %0, t; }"
        : "=r"(addr) : "l"(smem_ptr));
    asm volatile("ldmatrix.sync.aligned.m8n8.x4.shared.b16 {%0,%1,%2,%3}, [%4];"
                 : "=r"(r0), "=r"(r1), "=r"(r2), "=r"(r3) : "r"(addr));
}

__device__ __forceinline__ uint32_t smem_u32(const void* p) {
    uint32_t a;
    asm("{ .reg .u64 t; cvta.to.shared.u64 t, %1; cvt.u32.u64 %0, t; }"
        : "=r"(a) : "l"(p));
    return a;
}

#define CPA16(dst_u32, src_ptr) \
    asm volatile("cp.async.cg.shared.global [%0], [%1], 16;" :: "r"(dst_u32), "l"(src_ptr))
#define CPA_COMMIT() asm volatile("cp.async.commit_group;" ::: "memory")
#define CPA_WAIT1()  asm volatile("cp.async.wait_group 1;" ::: "memory")

// ---------------- prep ----------------

// blocks: [0,1040) we2ft | [1040,1104) gru | [1104,2128) zero agg/deg/scnt
__global__ void k_prep(const float* __restrict__ We2, const float* __restrict__ be2,
                       const float* __restrict__ Wih, const float* __restrict__ Whh) {
    int b = blockIdx.x, t = threadIdx.x;
    if (b < 1040) {
        int idx = b * 256 + t;               // < 4160*64
        int d = idx & 63, c = idx >> 6;
        float v;
        if (c < 4096) {
            int f = c >> 6, k = c & 63;
            v = We2[k * 4096 + d * 64 + f];
        } else {
            int f = c - 4096;
            v = be2[d * 64 + f];
        }
        g_We2FT[c * D + d] = __float2half(v);
    } else if (b < 1104) {
        int idx = (b - 1040) * 256 + t;      // < D*D*4
        int gg = idx & 3, f = (idx >> 2) & 63, k = idx >> 8;
        float vi = 0.f, vh = 0.f;
        if (gg < 3) {
            vi = Wih[(gg * 64 + f) * 64 + k];
            vh = Whh[(gg * 64 + f) * 64 + k];
        }
        g_Wi4[idx] = vi;
        g_Wh4[idx] = vh;
    } else {
        int idx = (b - 1104) * 256 + t;      // < N_NODES*D
        g_agg[idx] = 0.f;
        if (idx < N_NODES) { g_deg[idx] = 0.f; g_scnt[idx] = 0; }
    }
}

// node init + edge init + dst-deg + src-hist
__global__ void k_init(const float* __restrict__ x,
                       const float* __restrict__ W0,
                       const float* __restrict__ b0,
                       const float* __restrict__ ea,
                       const float* __restrict__ We1,
                       const float* __restrict__ be1,
                       const int* __restrict__ ei) {
    int gidx = blockIdx.x * blockDim.x + threadIdx.x;
    if (gidx < N_NODES * D) {
        int n = gidx >> 6, f = gidx & 63;
        float acc = b0[f];
        acc += x[n * 3 + 0] * W0[0 * D + f];
        acc += x[n * 3 + 1] * W0[1 * D + f];
        acc += x[n * 3 + 2] * W0[2 * D + f];
        float v = lrelu(acc);
        g_h[gidx] = v;
        g_h_h[gidx] = __float2half(v);
    } else {
        int idx = gidx - N_NODES * D;
        int e = idx >> 6, f = idx & 63;
        float acc = be1[f];
        acc += ea[e * 4 + 0] * We1[0 * D + f];
        acc += ea[e * 4 + 1] * We1[1 * D + f];
        acc += ea[e * 4 + 2] * We1[2 * D + f];
        acc += ea[e * 4 + 3] * We1[3 * D + f];
        g_he_h[idx] = __float2half(lrelu(acc));
        if (f == 0) {
            atomicAdd(&g_deg[ei[N_EDGES + e]], 1.f);
            atomicAdd(&g_scnt[ei[e]], 1);
        }
    }
}

// exclusive scan of scnt -> rowptr; zero fill
__global__ void k_scan() {
    __shared__ int ssum[1024];
    int t = threadIdx.x;
    int s0 = g_scnt[4 * t], s1 = g_scnt[4 * t + 1];
    int s2 = g_scnt[4 * t + 2], s3 = g_scnt[4 * t + 3];
    int loc = s0 + s1 + s2 + s3;
    ssum[t] = loc;
    __syncthreads();
    for (int off = 1; off < 1024; off <<= 1) {
        int v = (t >= off) ? ssum[t - off] : 0;
        __syncthreads();
        ssum[t] += v;
        __syncthreads();
    }
    int base = ssum[t] - loc;
    g_rowptr[4 * t]     = base;
    g_rowptr[4 * t + 1] = base + s0;
    g_rowptr[4 * t + 2] = base + s0 + s1;
    g_rowptr[4 * t + 3] = base + s0 + s1 + s2;
    g_fill[4 * t] = 0; g_fill[4 * t + 1] = 0;
    g_fill[4 * t + 2] = 0; g_fill[4 * t + 3] = 0;
    if (t == 1023) g_rowptr[N_NODES] = ssum[1023];
}

// scatter edges into src-grouped order; permute he + (src,dst)
__global__ void k_fill(const int* __restrict__ ei) {
    int e = blockIdx.x * blockDim.x + threadIdx.x;
    if (e >= N_EDGES) return;
    int src = ei[e];
    int pos = atomicAdd(&g_fill[src], 1);
    int slot = g_rowptr[src] + pos;
    g_sd_p[slot] = make_int2(src, ei[N_EDGES + e]);
    const uint4* s = (const uint4*)&g_he_h[e * D];
    uint4* d = (uint4*)&g_he_p[slot * D];
#pragma unroll
    for (int i = 0; i < 8; i++) d[i] = s[i];
}

// ---------------- fused T-chunk GEMM + message + scatter ----------------
// Block: 32 src nodes, their grouped edges (<=ECAP), 256 threads (8 warps 2m x 4n).
// Loop 16 chunks (4 f x 64 k): GEMM [32 x 64d] @ [256c x 64d]^T -> Tc smem,
// then per (edge, f-pair): dot(he, Tc row) + Tbias -> atomicAdd to agg.
// smem halfs layout:
#define OA     0
#define OBIAS  (OA + SRCB * 72)          // 2304
#define OB     (OBIAS + 64 * 72)         // 6912
#define OTB    (OB + 2 * 256 * 72)       // 43776
#define OTC    (OTB + SRCB * 72)         // 46080
#define OHE    (OTC + SRCB * 272)        // 54784
#define OSD    (OHE + ECAP * 72)         // 77824  (int2 area: ECAP*4 halfs)
#define FUSED_SMEM ((OSD + ECAP * 4) * 2)

__global__ void __launch_bounds__(256) k_fused() {
    extern __shared__ __half smem[];
    __half* sA  = smem + OA;
    __half* sBi = smem + OBIAS;
    __half* sB0 = smem + OB;
    __half* sTb = smem + OTB;
    __half* sTc = smem + OTC;
    __half* sHe = smem + OHE;
    int2*   sd  = (int2*)(smem + OSD);

    int nb = blockIdx.x * SRCB;
    int tid = threadIdx.x;
    int estart = g_rowptr[nb];
    int ecnt = g_rowptr[nb + SRCB] - estart;
    if (ecnt > ECAP) ecnt = ECAP;

    // loads: sA (256 uint4), sBias (512), sHe (ecnt*8), sd
    {
        int row = tid >> 3, ch = tid & 7;
        *(uint4*)&sA[row * 72 + ch * 8] = *(const uint4*)&g_h_h[(nb + row) * D + ch * 8];
    }
#pragma unroll
    for (int i = 0; i < 2; i++) {
        int u = tid + i * 256;
        int row = u >> 3, ch = u & 7;
        *(uint4*)&sBi[row * 72 + ch * 8] = *(const uint4*)&g_We2FT[(4096 + row) * D + ch * 8];
    }
    for (int u = tid; u < ecnt * 8; u += 256) {
        int row = u >> 3, ch = u & 7;
        *(uint4*)&sHe[row * 72 + ch * 8] = *(const uint4*)&g_he_p[(estart + row) * D + ch * 8];
    }
    for (int i = tid; i < ecnt; i += 256) sd[i] = g_sd_p[estart + i];

    // preload chunk 0 into sB[0]
#pragma unroll
    for (int i = 0; i < 8; i++) {
        int u = tid + i * 256;
        int row = u >> 3, ch = u & 7;
        CPA16(smem_u32(&sB0[row * 72 + ch * 8]),
              (const char*)&g_We2FT[row * D + ch * 8]);
    }
    CPA_COMMIT();

    int warp = tid >> 5, lane = tid & 31;
    int wm = warp & 1, wn = warp >> 1;      // 2m x 4n
    int g = lane >> 2, tig = lane & 3;
    int a_row = (lane & 7) + ((lane & 8) ? 8 : 0);
    int a_col8 = (lane & 16) ? 8 : 0;
    int b_row = (lane & 7) + ((lane & 16) ? 8 : 0);
    int b_col8 = (lane & 8) ? 8 : 0;

    __syncthreads();   // sA/sBi/sHe/sd visible

    // ---- bias GEMM: Tbias[32 x 64f] ----
    {
        float cb[2][4];
#pragma unroll
        for (int j = 0; j < 2; j++) cb[j][0] = cb[j][1] = cb[j][2] = cb[j][3] = 0.f;
#pragma unroll
        for (int s = 0; s < 4; s++) {
            int k0 = s * 16;
            uint32_t a0, a1, a2, a3, b0, b1, b2, b3;
            ldsm_x4(a0, a1, a2, a3, &sA[(wm * 16 + a_row) * 72 + k0 + a_col8]);
            ldsm_x4(b0, b1, b2, b3, &sBi[(wn * 16 + b_row) * 72 + k0 + b_col8]);
            mma16816(cb[0], a0, a1, a2, a3, b0, b1);
            mma16816(cb[1], a0, a1, a2, a3, b2, b3);
        }
#pragma unroll
        for (int j = 0; j < 2; j++) {
            int col = wn * 16 + j * 8 + 2 * tig;
            int r0 = wm * 16 + g;
            *(__half2*)&sTb[r0 * 72 + col] = __floats2half2_rn(cb[j][0], cb[j][1]);
            *(__half2*)&sTb[(r0 + 8) * 72 + col] = __floats2half2_rn(cb[j][2], cb[j][3]);
        }
    }

    // ---- chunk loop ----
    for (int ch = 0; ch < NCH; ch++) {
        int cur = ch & 1;
        __half* sB = sB0 + cur * 256 * 72;
        if (ch + 1 < NCH) {
            __half* sBn = sB0 + (1 - cur) * 256 * 72;
#pragma unroll
            for (int i = 0; i < 8; i++) {
                int u = tid + i * 256;
                int row = u >> 3, c8 = u & 7;
                CPA16(smem_u32(&sBn[row * 72 + c8 * 8]),
                      (const char*)&g_We2FT[((ch + 1) * 256 + row) * D + c8 * 8]);
            }
        }
        CPA_COMMIT();
        CPA_WAIT1();       // chunk ch resident
        __syncthreads();   // sB[cur] visible; prev msg done (Tc reusable); Tbias ready

        float c[8][4];
#pragma unroll
        for (int j = 0; j < 8; j++) c[j][0] = c[j][1] = c[j][2] = c[j][3] = 0.f;
#pragma unroll
        for (int s = 0; s < 4; s++) {
            int k0 = s * 16;
            uint32_t a0, a1, a2, a3;
            ldsm_x4(a0, a1, a2, a3, &sA[(wm * 16 + a_row) * 72 + k0 + a_col8]);
#pragma unroll
            for (int jp = 0; jp < 4; jp++) {
                uint32_t b0, b1, b2, b3;
                ldsm_x4(b0, b1, b2, b3,
                        &sB[(wn * 64 + jp * 16 + b_row) * 72 + k0 + b_col8]);
                mma16816(c[2 * jp],     a0, a1, a2, a3, b0, b1);
                mma16816(c[2 * jp + 1], a0, a1, a2, a3, b2, b3);
            }
        }
        // stage Tc: warp's 64 cols = exactly f-local wn; pos = wn*68 + klocal
#pragma unroll
        for (int j = 0; j < 8; j++) {
            int pos = wn * 68 + j * 8 + 2 * tig;
            int r0 = wm * 16 + g;
            *(__half2*)&sTc[r0 * 272 + pos] = __floats2half2_rn(c[j][0], c[j][1]);
            *(__half2*)&sTc[(r0 + 8) * 272 + pos] = __floats2half2_rn(c[j][2], c[j][3]);
        }
        __syncthreads();   // Tc visible

        // msg: task = (edge, f-pair) over chunk's 4 f
        int ntask = ecnt * 2;
        for (int task = tid; task < ntask; task += 256) {
            int e = task >> 1, fp = task & 1;
            int2 sdv = sd[e];
            int m = sdv.x - nb;
            int fa = ch * 4 + 2 * fp;
            float2 bi = __half22float2(*(__half2*)&sTb[m * 72 + fa]);
            float a0 = bi.x, a1 = bi.y;
            const uint32_t* he2 = (const uint32_t*)(sHe + e * 72);
            const __half* tc = sTc + m * 272 + 2 * fp * 68;
#pragma unroll 8
            for (int kp = 0; kp < 32; kp++) {
                float2 h2 = __half22float2(*(__half2*)&he2[kp]);
                float2 t0 = __half22float2(*(__half2*)&tc[2 * kp]);
                float2 t1 = __half22float2(*(__half2*)&tc[68 + 2 * kp]);
                a0 = fmaf(h2.x, t0.x, a0); a0 = fmaf(h2.y, t0.y, a0);
                a1 = fmaf(h2.x, t1.x, a1); a1 = fmaf(h2.y, t1.y, a1);
            }
            float* agg = &g_agg[sdv.y * D + fa];
            atomicAdd(agg, a0);
            atomicAdd(agg + 1, a1);
        }
        // next iteration's first __syncthreads closes the msg phase
    }
}

// ---------------- node update (proven R11 version) ----------------
__global__ void k_node_update(const float* __restrict__ root,
                              const float* __restrict__ conv_b,
                              const float* __restrict__ bih,
                              const float* __restrict__ bhh) {
    __shared__ float sh[16][D];
    __shared__ float sm[16][D];
    __shared__ float sroot[D][D];
    int nb = blockIdx.x * 16;
    int tid = threadIdx.x;
    int f = tid & 63, ng = tid >> 6;

#pragma unroll
    for (int i = 0; i < 4; i++) {
        int ln = ng + 4 * i;
        sh[ln][f] = g_h[(nb + ln) * D + f];
    }
#pragma unroll
    for (int i = 0; i < 16; i++) {
        int idx = tid + i * 256;
        sroot[idx >> 6][idx & 63] = root[idx];
    }
    __syncthreads();

    float cb = conv_b[f];
#pragma unroll
    for (int i = 0; i < 4; i++) {
        int ln = ng + 4 * i;
        int n = nb + ln;
        float invd = 1.f / fmaxf(g_deg[n], 1.f);
        float acc = g_agg[n * D + f] * invd + cb;
        g_agg[n * D + f] = 0.f;
#pragma unroll 8
        for (int d = 0; d < D; d++) acc += sh[ln][d] * sroot[d][f];
        sm[ln][f] = lrelu(acc);
    }
    __syncthreads();

    float gir[4], giz[4], gin[4], ghr[4], ghz[4], ghn[4];
    float bir = bih[f], biz = bih[D + f], bin = bih[2 * D + f];
    float bhr = bhh[f], bhz = bhh[D + f], bhn = bhh[2 * D + f];
#pragma unroll
    for (int i = 0; i < 4; i++) {
        gir[i] = bir; giz[i] = biz; gin[i] = bin;
        ghr[i] = bhr; ghz[i] = bhz; ghn[i] = bhn;
    }

#pragma unroll 4
    for (int k = 0; k < D; k++) {
        float4 wi = *(const float4*)&g_Wi4[(k * D + f) * 4];
        float4 wh = *(const float4*)&g_Wh4[(k * D + f) * 4];
#pragma unroll
        for (int i = 0; i < 4; i++) {
            int ln = ng + 4 * i;
            float mk = sm[ln][k];
            float hk = sh[ln][k];
            gir[i] += mk * wi.x; giz[i] += mk * wi.y; gin[i] += mk * wi.z;
            ghr[i] += hk * wh.x; ghz[i] += hk * wh.y; ghn[i] += hk * wh.z;
        }
    }

#pragma unroll
    for (int i = 0; i < 4; i++) {
        int ln = ng + 4 * i;
        float r  = sigm(gir[i] + ghr[i]);
        float z  = sigm(giz[i] + ghz[i]);
        float nn = tanhf(gin[i] + r * ghn[i]);
        float hv = (1.f - z) * nn + z * sh[ln][f];
        g_h[(nb + ln) * D + f] = hv;
        g_h_h[(nb + ln) * D + f] = __float2half(hv);
    }
}

// ---------------- set2set + head ----------------

__global__ void k_s2s_init(const float* __restrict__ lbih,
                           const float* __restrict__ lbhh) {
    int t = threadIdx.x;
    if (t < D) {
        float gi = lbih[t]         + lbhh[t];
        float gg = lbih[2 * D + t] + lbhh[2 * D + t];
        float go = lbih[3 * D + t] + lbhh[3 * D + t];
        float cl = sigm(gi) * tanhf(gg);
        g_q[t] = sigm(go) * tanhf(cl);
    }
    if (t < BG) { g_emax[t] = -3.4e38f; g_asum[t] = 0.f; }
    for (int i = t; i < BG * D; i += blockDim.x) g_rpool[i] = 0.f;
}

__global__ void k_dot(const int* __restrict__ batch) {
    int lane = threadIdx.x & 31;
    int warp = threadIdx.x >> 5;
    int n = blockIdx.x * 8 + warp;
    if (n >= N_NODES) return;
    float v = g_h[n * D + lane] * g_q[lane] + g_h[n * D + 32 + lane] * g_q[32 + lane];
#pragma unroll
    for (int o = 16; o > 0; o >>= 1) v += __shfl_down_sync(0xFFFFFFFFu, v, o);
    if (lane == 0) {
        g_e[n] = v;
        atomicMaxF(&g_emax[batch[n]], v);
    }
}

__global__ void k_exp(const int* __restrict__ batch) {
    int n = blockIdx.x * blockDim.x + threadIdx.x;
    if (n >= N_NODES) return;
    int g = batch[n];
    float a = expf(g_e[n] - g_emax[g]);
    g_a[n] = a;
    atomicAdd(&g_asum[g], a);
}

__global__ void k_pool(const int* __restrict__ batch) {
    int idx = blockIdx.x * blockDim.x + threadIdx.x;
    if (idx >= N_NODES * D) return;
    int n = idx >> 6, f = idx & 63;
    int g = batch[n];
    float w = g_a[n] / g_asum[g];
    atomicAdd(&g_rpool[g * D + f], w * g_h[idx]);
}

__global__ void k_out(const float* __restrict__ Wout,
                      const float* __restrict__ bout,
                      float* __restrict__ out) {
    int t = threadIdx.x;
    if (t >= BG * 2) return;
    int b = t >> 1, c = t & 1;
    float acc = bout[c];
#pragma unroll 8
    for (int j = 0; j < D; j++) {
        acc += g_q[j] * Wout[j * 2 + c];
        acc += g_rpool[b * D + j] * Wout[(D + j) * 2 + c];
    }
    out[b * 2 + c] = acc;
}

// ---------------- launch ----------------

extern "C" void kernel_launch(void* const* d_in, const int* in_sizes, int n_in,
                              void* d_out, int out_size) {
    const float* x      = (const float*)d_in[0];
    const float* ea     = (const float*)d_in[1];
    const int*   ei     = (const int*)d_in[2];
    const int*   batch  = (const int*)d_in[3];
    const float* W0     = (const float*)d_in[4];
    const float* b0     = (const float*)d_in[5];
    const float* We1    = (const float*)d_in[6];
    const float* be1    = (const float*)d_in[7];
    const float* We2    = (const float*)d_in[8];
    const float* be2    = (const float*)d_in[9];
    const float* root   = (const float*)d_in[10];
    const float* conv_b = (const float*)d_in[11];
    const float* Wih    = (const float*)d_in[12];
    const float* Whh    = (const float*)d_in[13];
    const float* bih    = (const float*)d_in[14];
    const float* bhh    = (const float*)d_in[15];
    const float* lbih   = (const float*)d_in[18];
    const float* lbhh   = (const float*)d_in[19];
    const float* Wout   = (const float*)d_in[20];
    const float* bout   = (const float*)d_in[21];
    float* out = (float*)d_out;
    (void)in_sizes; (void)n_in; (void)out_size;

    cudaFuncSetAttribute(k_fused, cudaFuncAttributeMaxDynamicSharedMemorySize, FUSED_SMEM);

    k_prep<<<2128, 256>>>(We2, be2, Wih, Whh);                      // 0
    k_init<<<(N_NODES * D + N_EDGES * D) / 256, 256>>>(x, W0, b0, ea, We1, be1, ei); // 1
    k_scan<<<1, 1024>>>();                                          // 2
    k_fill<<<N_EDGES / 256, 256>>>(ei);                             // 3  <- profiled slot
    for (int it = 0; it < 6; it++) {
        k_fused<<<N_NODES / SRCB, 256, FUSED_SMEM>>>();
        k_node_update<<<N_NODES / 16, 256>>>(root, conv_b, bih, bhh);
    }

    k_s2s_init<<<1, 256>>>(lbih, lbhh);
    k_dot<<<N_NODES / 8, 256>>>(batch);
    k_exp<<<(N_NODES + 255) / 256, 256>>>(batch);
    k_pool<<<(N_NODES * D) / 256, 256>>>(batch);
    k_out<<<1, 64>>>(Wout, bout, out);
}

// round 15
// speedup vs baseline: 1.1555x; 1.1555x over previous
#include <cuda_runtime.h>
#include <cuda_fp16.h>
#include <math.h>
#include <stdint.h>

#define N_NODES 4096
#define N_EDGES 16384
#define D       64
#define BG      16
#define SLOPE   0.01f

#define TW      4160            // T row width: 4096 (k*64+f) + 64 bias cols
#define TWPAD   4352            // padded to 17*256 for GEMM tiling

// ---------------- device scratch ----------------
__device__ __half g_T[(size_t)N_NODES * TW];     // 34 MB per-node transformed table
__device__ __half g_We2RT[TWPAD * D];            // [c][d] reshaped We2 (+bias cols)
__device__ __half g_he_h[N_EDGES * D];
__device__ __half g_h_h[N_NODES * D];            // fp16 mirror of h
__device__ float g_h[N_NODES * D];
__device__ float g_agg[N_NODES * D];
__device__ float g_deg[N_NODES];
__device__ float g_Wi4[D * D * 4];
__device__ float g_Wh4[D * D * 4];
__device__ float g_q[D];
__device__ float g_a[N_NODES];
__device__ float g_asum[BG];
__device__ float g_rpool[BG * D];

__device__ __forceinline__ float lrelu(float x) { return x >= 0.f ? x : SLOPE * x; }
__device__ __forceinline__ float sigm(float x)  { return 1.f / (1.f + expf(-x)); }

__device__ __forceinline__ void mma16816(float c[4],
                                         uint32_t a0, uint32_t a1, uint32_t a2, uint32_t a3,
                                         uint32_t b0, uint32_t b1) {
    asm volatile(
        "mma.sync.aligned.m16n8k16.row.col.f32.f16.f16.f32 "
        "{%0,%1,%2,%3}, {%4,%5,%6,%7}, {%8,%9}, {%0,%1,%2,%3};"
        : "+f"(c[0]), "+f"(c[1]), "+f"(c[2]), "+f"(c[3])
        : "r"(a0), "r"(a1), "r"(a2), "r"(a3), "r"(b0), "r"(b1));
}

__device__ __forceinline__ void ldsm_x4(uint32_t& r0, uint32_t& r1,
                                        uint32_t& r2, uint32_t& r3,
                                        const void* smem_ptr) {
    uint32_t addr;
    asm("{ .reg .u64 t; cvta.to.shared.u64 t, %1; cvt.u32.u64 %0, t; }"
        : "=r"(addr) : "l"(smem_ptr));
    asm volatile("ldmatrix.sync.aligned.m8n8.x4.shared.b16 {%0,%1,%2,%3}, [%4];"
                 : "=r"(r0), "=r"(r1), "=r"(r2), "=r"(r3) : "r"(addr));
}

// ---------------- prep (fused) ----------------

// sections: [0,1088) we2rt | [1088,1152) gru | [1152,2176) zero agg/deg
__global__ void k_prep(const float* __restrict__ We2, const float* __restrict__ be2,
                       const float* __restrict__ Wih, const float* __restrict__ Whh) {
    int b = blockIdx.x;
    int t = threadIdx.x;
    if (b < 1088) {
        int idx = b * 256 + t;                 // < TWPAD*D
        int d = idx & 63, c = idx >> 6;
        float v = 0.f;
        if (c < 4096) {
            int k = c >> 6, f = c & 63;
            v = We2[k * 4096 + d * 64 + f];
        } else if (c < TW) {
            int f = c - 4096;
            v = be2[d * 64 + f];
        }
        g_We2RT[c * D + d] = __float2half(v);
    } else if (b < 1152) {
        int idx = (b - 1088) * 256 + t;        // < D*D*4
        int gg = idx & 3, f = (idx >> 2) & 63, k = idx >> 8;
        float vi = 0.f, vh = 0.f;
        if (gg < 3) {
            vi = Wih[(gg * 64 + f) * 64 + k];
            vh = Whh[(gg * 64 + f) * 64 + k];
        }
        g_Wi4[idx] = vi;
        g_Wh4[idx] = vh;
    } else {
        int idx = (b - 1152) * 256 + t;        // < N_NODES*D
        g_agg[idx] = 0.f;
        if (idx < N_NODES) g_deg[idx] = 0.f;
    }
}

// node init + edge init + dst-deg
__global__ void k_init(const float* __restrict__ x,
                       const float* __restrict__ W0,
                       const float* __restrict__ b0,
                       const float* __restrict__ ea,
                       const float* __restrict__ We1,
                       const float* __restrict__ be1,
                       const int* __restrict__ ei) {
    int gidx = blockIdx.x * blockDim.x + threadIdx.x;
    if (gidx < N_NODES * D) {
        int n = gidx >> 6, f = gidx & 63;
        float acc = b0[f];
        acc += x[n * 3 + 0] * W0[0 * D + f];
        acc += x[n * 3 + 1] * W0[1 * D + f];
        acc += x[n * 3 + 2] * W0[2 * D + f];
        float v = lrelu(acc);
        g_h[gidx] = v;
        g_h_h[gidx] = __float2half(v);
    } else {
        int idx = gidx - N_NODES * D;
        int e = idx >> 6, f = idx & 63;
        float acc = be1[f];
        acc += ea[e * 4 + 0] * We1[0 * D + f];
        acc += ea[e * 4 + 1] * We1[1 * D + f];
        acc += ea[e * 4 + 2] * We1[2 * D + f];
        acc += ea[e * 4 + 3] * We1[3 * D + f];
        g_he_h[idx] = __float2half(lrelu(acc));
        if (f == 0) {
            atomicAdd(&g_deg[ei[N_EDGES + e]], 1.f);
        }
    }
}

// ---------------- per-iteration T GEMM (proven R11 version) ----------------
// Block: 256 nodes x 256 cols (4 x 64-row phases); 512 thr; warps 2wm x 8wn.
__global__ void __launch_bounds__(512, 2) k_t_gemm() {
    extern __shared__ __half smem[];
    __half* sBT = smem;                 // [256][72]
    __half* sA  = smem + 256 * 72;      // [64][72]
    __half* sSt = smem + 320 * 72;      // [64][264]
    int nbase = blockIdx.x * 256;
    int mbase0 = blockIdx.y * 256;
    int tid = threadIdx.x;

#pragma unroll
    for (int i = 0; i < 4; i++) {
        int u = tid + i * 512;
        int row = u >> 3, ch = u & 7;
        *(uint4*)&sBT[row * 72 + ch * 8] = *(const uint4*)&g_We2RT[(nbase + row) * D + ch * 8];
    }

    int warp = tid >> 5, lane = tid & 31;
    int wm = warp & 1, wn = warp >> 1;
    int g = lane >> 2, tig = lane & 3;
    int a_row = (lane & 7) + ((lane & 8) ? 8 : 0);
    int a_col8 = (lane & 16) ? 8 : 0;
    int b_row = (lane & 7) + ((lane & 16) ? 8 : 0);
    int b_col8 = (lane & 8) ? 8 : 0;

#pragma unroll
    for (int ms = 0; ms < 4; ms++) {
        int mbase = mbase0 + ms * 64;
        __syncthreads();
        {
            int row = tid >> 3, ch = tid & 7;
            *(uint4*)&sA[row * 72 + ch * 8] = *(const uint4*)&g_h_h[(mbase + row) * D + ch * 8];
        }
        __syncthreads();

        float c[2][4][4];
#pragma unroll
        for (int t = 0; t < 2; t++)
#pragma unroll
            for (int j = 0; j < 4; j++)
                c[t][j][0] = c[t][j][1] = c[t][j][2] = c[t][j][3] = 0.f;

#pragma unroll
        for (int s = 0; s < 4; s++) {
            int k0 = s * 16;
            uint32_t a[2][4], b[2][4];
#pragma unroll
            for (int t = 0; t < 2; t++)
                ldsm_x4(a[t][0], a[t][1], a[t][2], a[t][3],
                        &sA[(wm * 32 + t * 16 + a_row) * 72 + k0 + a_col8]);
#pragma unroll
            for (int jp = 0; jp < 2; jp++)
                ldsm_x4(b[jp][0], b[jp][1], b[jp][2], b[jp][3],
                        &sBT[(wn * 32 + jp * 16 + b_row) * 72 + k0 + b_col8]);
#pragma unroll
            for (int t = 0; t < 2; t++)
#pragma unroll
                for (int jp = 0; jp < 2; jp++) {
                    mma16816(c[t][2 * jp],     a[t][0], a[t][1], a[t][2], a[t][3],
                             b[jp][0], b[jp][1]);
                    mma16816(c[t][2 * jp + 1], a[t][0], a[t][1], a[t][2], a[t][3],
                             b[jp][2], b[jp][3]);
                }
        }

#pragma unroll
        for (int t = 0; t < 2; t++)
#pragma unroll
            for (int j = 0; j < 4; j++) {
                int col = wn * 32 + j * 8 + 2 * tig;
                int r0 = wm * 32 + t * 16 + g;
                *(__half2*)&sSt[r0 * 264 + col] = __floats2half2_rn(c[t][j][0], c[t][j][1]);
                *(__half2*)&sSt[(r0 + 8) * 264 + col] = __floats2half2_rn(c[t][j][2], c[t][j][3]);
            }
        __syncthreads();

#pragma unroll
        for (int i = 0; i < 4; i++) {
            int u = tid + i * 512;
            int row = u >> 5, seg = u & 31;
            int col = nbase + seg * 8;
            if (col < TW)
                *(uint4*)&g_T[(size_t)(mbase + row) * TW + col] =
                    *(uint4*)&sSt[row * 264 + seg * 8];
        }
    }
}

// ---------------- msg (proven R11 version, unroll 16) ----------------
// 16 edges/block (256 thr): 2 edges/warp, 16 lanes/edge, 4 cols/lane (LDG.64).
__global__ void k_msg(const int* __restrict__ ei) {
    int tid = threadIdx.x;
    int warp = tid >> 5, lane = tid & 31;
    int half = lane >> 4, sl = lane & 15;
    int le = warp * 2 + half;
    int e = blockIdx.x * 16 + le;
    __shared__ float sx[16][D];
#pragma unroll
    for (int i = 0; i < 4; i++) {
        int idx = tid + i * 256;
        int l2 = idx >> 6, k = idx & 63;
        sx[l2][k] = __half2float(g_he_h[(blockIdx.x * 16 + l2) * D + k]);
    }
    __syncthreads();

    int src = ei[e];
    int dst = ei[N_EDGES + e];
    const __half* __restrict__ T = g_T + (size_t)src * TW;

    float a0, a1, a2, a3;
    {
        uint2 b = *(const uint2*)&T[4096 + 4 * sl];
        float2 b01 = __half22float2(*(__half2*)&b.x);
        float2 b23 = __half22float2(*(__half2*)&b.y);
        a0 = b01.x; a1 = b01.y; a2 = b23.x; a3 = b23.y;
    }
#pragma unroll 16
    for (int k = 0; k < D; k++) {
        uint2 w = *(const uint2*)&T[k * 64 + 4 * sl];
        float2 w01 = __half22float2(*(__half2*)&w.x);
        float2 w23 = __half22float2(*(__half2*)&w.y);
        float hv = sx[le][k];
        a0 = fmaf(hv, w01.x, a0);
        a1 = fmaf(hv, w01.y, a1);
        a2 = fmaf(hv, w23.x, a2);
        a3 = fmaf(hv, w23.y, a3);
    }
    float* agg = &g_agg[dst * D + 4 * sl];
    atomicAdd(agg + 0, a0);
    atomicAdd(agg + 1, a1);
    atomicAdd(agg + 2, a2);
    atomicAdd(agg + 3, a3);
}

// ---------------- node update (proven R11 version) ----------------
__global__ void k_node_update(const float* __restrict__ root,
                              const float* __restrict__ conv_b,
                              const float* __restrict__ bih,
                              const float* __restrict__ bhh) {
    __shared__ float sh[16][D];
    __shared__ float sm[16][D];
    __shared__ float sroot[D][D];
    int nb = blockIdx.x * 16;
    int tid = threadIdx.x;
    int f = tid & 63, ng = tid >> 6;

#pragma unroll
    for (int i = 0; i < 4; i++) {
        int ln = ng + 4 * i;
        sh[ln][f] = g_h[(nb + ln) * D + f];
    }
#pragma unroll
    for (int i = 0; i < 16; i++) {
        int idx = tid + i * 256;
        sroot[idx >> 6][idx & 63] = root[idx];
    }
    __syncthreads();

    float cb = conv_b[f];
#pragma unroll
    for (int i = 0; i < 4; i++) {
        int ln = ng + 4 * i;
        int n = nb + ln;
        float invd = 1.f / fmaxf(g_deg[n], 1.f);
        float acc = g_agg[n * D + f] * invd + cb;
        g_agg[n * D + f] = 0.f;
#pragma unroll 8
        for (int d = 0; d < D; d++) acc += sh[ln][d] * sroot[d][f];
        sm[ln][f] = lrelu(acc);
    }
    __syncthreads();

    float gir[4], giz[4], gin[4], ghr[4], ghz[4], ghn[4];
    float bir = bih[f], biz = bih[D + f], bin = bih[2 * D + f];
    float bhr = bhh[f], bhz = bhh[D + f], bhn = bhh[2 * D + f];
#pragma unroll
    for (int i = 0; i < 4; i++) {
        gir[i] = bir; giz[i] = biz; gin[i] = bin;
        ghr[i] = bhr; ghz[i] = bhz; ghn[i] = bhn;
    }

#pragma unroll 4
    for (int k = 0; k < D; k++) {
        float4 wi = *(const float4*)&g_Wi4[(k * D + f) * 4];
        float4 wh = *(const float4*)&g_Wh4[(k * D + f) * 4];
#pragma unroll
        for (int i = 0; i < 4; i++) {
            int ln = ng + 4 * i;
            float mk = sm[ln][k];
            float hk = sh[ln][k];
            gir[i] += mk * wi.x; giz[i] += mk * wi.y; gin[i] += mk * wi.z;
            ghr[i] += hk * wh.x; ghz[i] += hk * wh.y; ghn[i] += hk * wh.z;
        }
    }

#pragma unroll
    for (int i = 0; i < 4; i++) {
        int ln = ng + 4 * i;
        float r  = sigm(gir[i] + ghr[i]);
        float z  = sigm(giz[i] + ghz[i]);
        float nn = tanhf(gin[i] + r * ghn[i]);
        float hv = (1.f - z) * nn + z * sh[ln][f];
        g_h[(nb + ln) * D + f] = hv;
        g_h_h[(nb + ln) * D + f] = __float2half(hv);
    }
}

// ---------------- set2set + head (trimmed) ----------------

__global__ void k_s2s_init(const float* __restrict__ lbih,
                           const float* __restrict__ lbhh) {
    int t = threadIdx.x;
    if (t < D) {
        float gi = lbih[t]         + lbhh[t];
        float gg = lbih[2 * D + t] + lbhh[2 * D + t];
        float go = lbih[3 * D + t] + lbhh[3 * D + t];
        float cl = sigm(gi) * tanhf(gg);
        g_q[t] = sigm(go) * tanhf(cl);
    }
    if (t < BG) g_asum[t] = 0.f;
    for (int i = t; i < BG * D; i += blockDim.x) g_rpool[i] = 0.f;
}

// e[n] = dot(h[n], q); a = exp(e) (no max-shift: ratio identical, |e| small);
// atomicAdd per-graph sum.
__global__ void k_dote(const int* __restrict__ batch) {
    int lane = threadIdx.x & 31;
    int warp = threadIdx.x >> 5;
    int n = blockIdx.x * 8 + warp;
    if (n >= N_NODES) return;
    float v = g_h[n * D + lane] * g_q[lane] + g_h[n * D + 32 + lane] * g_q[32 + lane];
#pragma unroll
    for (int o = 16; o > 0; o >>= 1) v += __shfl_down_sync(0xFFFFFFFFu, v, o);
    if (lane == 0) {
        float a = expf(v);
        g_a[n] = a;
        atomicAdd(&g_asum[batch[n]], a);
    }
}

__global__ void k_pool(const int* __restrict__ batch) {
    int idx = blockIdx.x * blockDim.x + threadIdx.x;
    if (idx >= N_NODES * D) return;
    int n = idx >> 6, f = idx & 63;
    int g = batch[n];
    float w = g_a[n] / g_asum[g];
    atomicAdd(&g_rpool[g * D + f], w * g_h[idx]);
}

__global__ void k_out(const float* __restrict__ Wout,
                      const float* __restrict__ bout,
                      float* __restrict__ out) {
    int t = threadIdx.x;
    if (t >= BG * 2) return;
    int b = t >> 1, c = t & 1;
    float acc = bout[c];
#pragma unroll 8
    for (int j = 0; j < D; j++) {
        acc += g_q[j] * Wout[j * 2 + c];
        acc += g_rpool[b * D + j] * Wout[(D + j) * 2 + c];
    }
    out[b * 2 + c] = acc;
}

// ---------------- launch ----------------

extern "C" void kernel_launch(void* const* d_in, const int* in_sizes, int n_in,
                              void* d_out, int out_size) {
    const float* x      = (const float*)d_in[0];
    const float* ea     = (const float*)d_in[1];
    const int*   ei     = (const int*)d_in[2];
    const int*   batch  = (const int*)d_in[3];
    const float* W0     = (const float*)d_in[4];
    const float* b0     = (const float*)d_in[5];
    const float* We1    = (const float*)d_in[6];
    const float* be1    = (const float*)d_in[7];
    const float* We2    = (const float*)d_in[8];
    const float* be2    = (const float*)d_in[9];
    const float* root   = (const float*)d_in[10];
    const float* conv_b = (const float*)d_in[11];
    const float* Wih    = (const float*)d_in[12];
    const float* Whh    = (const float*)d_in[13];
    const float* bih    = (const float*)d_in[14];
    const float* bhh    = (const float*)d_in[15];
    const float* lbih   = (const float*)d_in[18];
    const float* lbhh   = (const float*)d_in[19];
    const float* Wout   = (const float*)d_in[20];
    const float* bout   = (const float*)d_in[21];
    float* out = (float*)d_out;
    (void)in_sizes; (void)n_in; (void)out_size;

    const int TGEMM_SMEM = (256 * 72 + 64 * 72 + 64 * 264) * (int)sizeof(__half); // 79872
    cudaFuncSetAttribute(k_t_gemm, cudaFuncAttributeMaxDynamicSharedMemorySize, TGEMM_SMEM);

    dim3 tgrid(17, N_NODES / 256);   // 272 blocks = 1 wave @ 2 blocks/SM

    // launch index 3 (ncu capture slot) = first k_msg
    k_prep<<<2176, 256>>>(We2, be2, Wih, Whh);                      // 0
    k_init<<<(N_NODES * D + N_EDGES * D) / 256, 256>>>(x, W0, b0, ea, We1, be1, ei); // 1
    k_t_gemm<<<tgrid, 512, TGEMM_SMEM>>>();                         // 2
    k_msg<<<N_EDGES / 16, 256>>>(ei);                               // 3  <- profiled
    k_node_update<<<N_NODES / 16, 256>>>(root, conv_b, bih, bhh);   // 4

    for (int it = 1; it < 6; it++) {
        k_t_gemm<<<tgrid, 512, TGEMM_SMEM>>>();
        k_msg<<<N_EDGES / 16, 256>>>(ei);
        k_node_update<<<N_NODES / 16, 256>>>(root, conv_b, bih, bhh);
    }

    k_s2s_init<<<1, 256>>>(lbih, lbhh);
    k_dote<<<N_NODES / 8, 256>>>(batch);
    k_pool<<<(N_NODES * D) / 256, 256>>>(batch);
    k_out<<<1, 64>>>(Wout, bout, out);
}

// round 16
// speedup vs baseline: 1.1968x; 1.0357x over previous
#include <cuda_runtime.h>
#include <cuda_fp16.h>
#include <math.h>
#include <stdint.h>

#define N_NODES 4096
#define N_EDGES 16384
#define D       64
#define BG      16
#define SLOPE   0.01f

#define TW      4160            // T row width: 4096 (k*64+f) + 64 bias cols
#define TWPAD   4352            // padded for GEMM tiling

// ---------------- device scratch ----------------
__device__ __half g_T[(size_t)N_NODES * TW];     // 34 MB per-node transformed table
__device__ __half g_We2RT[TWPAD * D];            // [c][d] reshaped We2 (+bias cols)
__device__ __half g_he_h[N_EDGES * D];
__device__ __half g_h_h[N_NODES * D];            // fp16 mirror of h
__device__ float g_h[N_NODES * D];
__device__ float g_agg[N_NODES * D];
__device__ float g_deg[N_NODES];
__device__ float g_Wi4[D * D * 4];
__device__ float g_Wh4[D * D * 4];
__device__ float g_q[D];
__device__ float g_a[N_NODES];
__device__ float g_asum[BG];
__device__ float g_rpool[BG * D];

__device__ __forceinline__ float lrelu(float x) { return x >= 0.f ? x : SLOPE * x; }
__device__ __forceinline__ float sigm(float x)  { return 1.f / (1.f + expf(-x)); }

__device__ __forceinline__ void mma16816(float c[4],
                                         uint32_t a0, uint32_t a1, uint32_t a2, uint32_t a3,
                                         uint32_t b0, uint32_t b1) {
    asm volatile(
        "mma.sync.aligned.m16n8k16.row.col.f32.f16.f16.f32 "
        "{%0,%1,%2,%3}, {%4,%5,%6,%7}, {%8,%9}, {%0,%1,%2,%3};"
        : "+f"(c[0]), "+f"(c[1]), "+f"(c[2]), "+f"(c[3])
        : "r"(a0), "r"(a1), "r"(a2), "r"(a3), "r"(b0), "r"(b1));
}

__device__ __forceinline__ void ldsm_x4(uint32_t& r0, uint32_t& r1,
                                        uint32_t& r2, uint32_t& r3,
                                        const void* smem_ptr) {
    uint32_t addr;
    asm("{ .reg .u64 t; cvta.to.shared.u64 t, %1; cvt.u32.u64 %0, t; }"
        : "=r"(addr) : "l"(smem_ptr));
    asm volatile("ldmatrix.sync.aligned.m8n8.x4.shared.b16 {%0,%1,%2,%3}, [%4];"
                 : "=r"(r0), "=r"(r1), "=r"(r2), "=r"(r3) : "r"(addr));
}

// ---------------- prep (fused) ----------------

// sections: [0,1088) we2rt | [1088,1152) gru | [1152,2176) zero agg/deg
__global__ void k_prep(const float* __restrict__ We2, const float* __restrict__ be2,
                       const float* __restrict__ Wih, const float* __restrict__ Whh) {
    int b = blockIdx.x;
    int t = threadIdx.x;
    if (b < 1088) {
        int idx = b * 256 + t;                 // < TWPAD*D
        int d = idx & 63, c = idx >> 6;
        float v = 0.f;
        if (c < 4096) {
            int k = c >> 6, f = c & 63;
            v = We2[k * 4096 + d * 64 + f];
        } else if (c < TW) {
            int f = c - 4096;
            v = be2[d * 64 + f];
        }
        g_We2RT[c * D + d] = __float2half(v);
    } else if (b < 1152) {
        int idx = (b - 1088) * 256 + t;        // < D*D*4
        int gg = idx & 3, f = (idx >> 2) & 63, k = idx >> 8;
        float vi = 0.f, vh = 0.f;
        if (gg < 3) {
            vi = Wih[(gg * 64 + f) * 64 + k];
            vh = Whh[(gg * 64 + f) * 64 + k];
        }
        g_Wi4[idx] = vi;
        g_Wh4[idx] = vh;
    } else {
        int idx = (b - 1152) * 256 + t;        // < N_NODES*D
        g_agg[idx] = 0.f;
        if (idx < N_NODES) g_deg[idx] = 0.f;
    }
}

// node init + edge init + dst-deg
__global__ void k_init(const float* __restrict__ x,
                       const float* __restrict__ W0,
                       const float* __restrict__ b0,
                       const float* __restrict__ ea,
                       const float* __restrict__ We1,
                       const float* __restrict__ be1,
                       const int* __restrict__ ei) {
    int gidx = blockIdx.x * blockDim.x + threadIdx.x;
    if (gidx < N_NODES * D) {
        int n = gidx >> 6, f = gidx & 63;
        float acc = b0[f];
        acc += x[n * 3 + 0] * W0[0 * D + f];
        acc += x[n * 3 + 1] * W0[1 * D + f];
        acc += x[n * 3 + 2] * W0[2 * D + f];
        float v = lrelu(acc);
        g_h[gidx] = v;
        g_h_h[gidx] = __float2half(v);
    } else {
        int idx = gidx - N_NODES * D;
        int e = idx >> 6, f = idx & 63;
        float acc = be1[f];
        acc += ea[e * 4 + 0] * We1[0 * D + f];
        acc += ea[e * 4 + 1] * We1[1 * D + f];
        acc += ea[e * 4 + 2] * We1[2 * D + f];
        acc += ea[e * 4 + 3] * We1[3 * D + f];
        g_he_h[idx] = __float2half(lrelu(acc));
        if (f == 0) {
            atomicAdd(&g_deg[ei[N_EDGES + e]], 1.f);
        }
    }
}

// ---------------- per-iteration T GEMM (high-occupancy 128-col tile) ----------------
// T[n][c] = sum_d h[n,d] * We2RT[c][d], fp16 out.
// Block: 256 nodes x 128 cols (4 x 64-row phases); 256 thr; warps 2wm x 4wn, m32 x n32.
// smem 44 KB -> 5 blocks/SM (40 warps).
__global__ void __launch_bounds__(256) k_t_gemm() {
    extern __shared__ __half smem[];
    __half* sBT = smem;                 // [128][72]
    __half* sA  = smem + 128 * 72;      // [64][72]
    __half* sSt = smem + 192 * 72;      // [64][136]
    int nbase = blockIdx.x * 128;
    int mbase0 = blockIdx.y * 256;
    int tid = threadIdx.x;

#pragma unroll
    for (int i = 0; i < 4; i++) {
        int u = tid + i * 256;          // 1024 uint4 = 128 rows x 8
        int row = u >> 3, ch = u & 7;
        *(uint4*)&sBT[row * 72 + ch * 8] = *(const uint4*)&g_We2RT[(nbase + row) * D + ch * 8];
    }

    int warp = tid >> 5, lane = tid & 31;
    int wm = warp & 1, wn = warp >> 1;   // 2m x 4n
    int g = lane >> 2, tig = lane & 3;
    int a_row = (lane & 7) + ((lane & 8) ? 8 : 0);
    int a_col8 = (lane & 16) ? 8 : 0;
    int b_row = (lane & 7) + ((lane & 16) ? 8 : 0);
    int b_col8 = (lane & 8) ? 8 : 0;

#pragma unroll
    for (int ms = 0; ms < 4; ms++) {
        int mbase = mbase0 + ms * 64;
        __syncthreads();   // prev copy-out done; sBT visible first time
        {
#pragma unroll
            for (int i = 0; i < 2; i++) {
                int u = tid + i * 256;   // 512 uint4 = 64 rows x 8
                int row = u >> 3, ch = u & 7;
                *(uint4*)&sA[row * 72 + ch * 8] = *(const uint4*)&g_h_h[(mbase + row) * D + ch * 8];
            }
        }
        __syncthreads();

        float c[2][4][4];
#pragma unroll
        for (int t = 0; t < 2; t++)
#pragma unroll
            for (int j = 0; j < 4; j++)
                c[t][j][0] = c[t][j][1] = c[t][j][2] = c[t][j][3] = 0.f;

#pragma unroll
        for (int s = 0; s < 4; s++) {
            int k0 = s * 16;
            uint32_t a[2][4], b[2][4];
#pragma unroll
            for (int t = 0; t < 2; t++)
                ldsm_x4(a[t][0], a[t][1], a[t][2], a[t][3],
                        &sA[(wm * 32 + t * 16 + a_row) * 72 + k0 + a_col8]);
#pragma unroll
            for (int jp = 0; jp < 2; jp++)
                ldsm_x4(b[jp][0], b[jp][1], b[jp][2], b[jp][3],
                        &sBT[(wn * 32 + jp * 16 + b_row) * 72 + k0 + b_col8]);
#pragma unroll
            for (int t = 0; t < 2; t++)
#pragma unroll
                for (int jp = 0; jp < 2; jp++) {
                    mma16816(c[t][2 * jp],     a[t][0], a[t][1], a[t][2], a[t][3],
                             b[jp][0], b[jp][1]);
                    mma16816(c[t][2 * jp + 1], a[t][0], a[t][1], a[t][2], a[t][3],
                             b[jp][2], b[jp][3]);
                }
        }

        // stage fragments (sSt stride 136 halfs -> word stride 68 == 4 mod 32:
        // banks = 4g + tig, conflict-free)
#pragma unroll
        for (int t = 0; t < 2; t++)
#pragma unroll
            for (int j = 0; j < 4; j++) {
                int col = wn * 32 + j * 8 + 2 * tig;
                int r0 = wm * 32 + t * 16 + g;
                *(__half2*)&sSt[r0 * 136 + col] = __floats2half2_rn(c[t][j][0], c[t][j][1]);
                *(__half2*)&sSt[(r0 + 8) * 136 + col] = __floats2half2_rn(c[t][j][2], c[t][j][3]);
            }
        __syncthreads();

        // coalesced copy-out: 64 rows x 128 cols = 1024 uint4
#pragma unroll
        for (int i = 0; i < 4; i++) {
            int u = tid + i * 256;
            int row = u >> 4, seg = u & 15;
            int col = nbase + seg * 8;
            if (col < TW)
                *(uint4*)&g_T[(size_t)(mbase + row) * TW + col] =
                    *(uint4*)&sSt[row * 136 + seg * 8];
        }
    }
}

// ---------------- msg (proven R15 version) ----------------
// 16 edges/block (256 thr): 2 edges/warp, 16 lanes/edge, 4 cols/lane (LDG.64).
__global__ void k_msg(const int* __restrict__ ei) {
    int tid = threadIdx.x;
    int warp = tid >> 5, lane = tid & 31;
    int half = lane >> 4, sl = lane & 15;
    int le = warp * 2 + half;
    int e = blockIdx.x * 16 + le;
    __shared__ float sx[16][D];
#pragma unroll
    for (int i = 0; i < 4; i++) {
        int idx = tid + i * 256;
        int l2 = idx >> 6, k = idx & 63;
        sx[l2][k] = __half2float(g_he_h[(blockIdx.x * 16 + l2) * D + k]);
    }
    __syncthreads();

    int src = ei[e];
    int dst = ei[N_EDGES + e];
    const __half* __restrict__ T = g_T + (size_t)src * TW;

    float a0, a1, a2, a3;
    {
        uint2 b = *(const uint2*)&T[4096 + 4 * sl];
        float2 b01 = __half22float2(*(__half2*)&b.x);
        float2 b23 = __half22float2(*(__half2*)&b.y);
        a0 = b01.x; a1 = b01.y; a2 = b23.x; a3 = b23.y;
    }
#pragma unroll 16
    for (int k = 0; k < D; k++) {
        uint2 w = *(const uint2*)&T[k * 64 + 4 * sl];
        float2 w01 = __half22float2(*(__half2*)&w.x);
        float2 w23 = __half22float2(*(__half2*)&w.y);
        float hv = sx[le][k];
        a0 = fmaf(hv, w01.x, a0);
        a1 = fmaf(hv, w01.y, a1);
        a2 = fmaf(hv, w23.x, a2);
        a3 = fmaf(hv, w23.y, a3);
    }
    float* agg = &g_agg[dst * D + 4 * sl];
    atomicAdd(agg + 0, a0);
    atomicAdd(agg + 1, a1);
    atomicAdd(agg + 2, a2);
    atomicAdd(agg + 3, a3);
}

// ---------------- node update (proven R11 version) ----------------
__global__ void k_node_update(const float* __restrict__ root,
                              const float* __restrict__ conv_b,
                              const float* __restrict__ bih,
                              const float* __restrict__ bhh) {
    __shared__ float sh[16][D];
    __shared__ float sm[16][D];
    __shared__ float sroot[D][D];
    int nb = blockIdx.x * 16;
    int tid = threadIdx.x;
    int f = tid & 63, ng = tid >> 6;

#pragma unroll
    for (int i = 0; i < 4; i++) {
        int ln = ng + 4 * i;
        sh[ln][f] = g_h[(nb + ln) * D + f];
    }
#pragma unroll
    for (int i = 0; i < 16; i++) {
        int idx = tid + i * 256;
        sroot[idx >> 6][idx & 63] = root[idx];
    }
    __syncthreads();

    float cb = conv_b[f];
#pragma unroll
    for (int i = 0; i < 4; i++) {
        int ln = ng + 4 * i;
        int n = nb + ln;
        float invd = 1.f / fmaxf(g_deg[n], 1.f);
        float acc = g_agg[n * D + f] * invd + cb;
        g_agg[n * D + f] = 0.f;
#pragma unroll 8
        for (int d = 0; d < D; d++) acc += sh[ln][d] * sroot[d][f];
        sm[ln][f] = lrelu(acc);
    }
    __syncthreads();

    float gir[4], giz[4], gin[4], ghr[4], ghz[4], ghn[4];
    float bir = bih[f], biz = bih[D + f], bin = bih[2 * D + f];
    float bhr = bhh[f], bhz = bhh[D + f], bhn = bhh[2 * D + f];
#pragma unroll
    for (int i = 0; i < 4; i++) {
        gir[i] = bir; giz[i] = biz; gin[i] = bin;
        ghr[i] = bhr; ghz[i] = bhz; ghn[i] = bhn;
    }

#pragma unroll 4
    for (int k = 0; k < D; k++) {
        float4 wi = *(const float4*)&g_Wi4[(k * D + f) * 4];
        float4 wh = *(const float4*)&g_Wh4[(k * D + f) * 4];
#pragma unroll
        for (int i = 0; i < 4; i++) {
            int ln = ng + 4 * i;
            float mk = sm[ln][k];
            float hk = sh[ln][k];
            gir[i] += mk * wi.x; giz[i] += mk * wi.y; gin[i] += mk * wi.z;
            ghr[i] += hk * wh.x; ghz[i] += hk * wh.y; ghn[i] += hk * wh.z;
        }
    }

#pragma unroll
    for (int i = 0; i < 4; i++) {
        int ln = ng + 4 * i;
        float r  = sigm(gir[i] + ghr[i]);
        float z  = sigm(giz[i] + ghz[i]);
        float nn = tanhf(gin[i] + r * ghn[i]);
        float hv = (1.f - z) * nn + z * sh[ln][f];
        g_h[(nb + ln) * D + f] = hv;
        g_h_h[(nb + ln) * D + f] = __float2half(hv);
    }
}

// ---------------- set2set + head (trimmed) ----------------

__global__ void k_s2s_init(const float* __restrict__ lbih,
                           const float* __restrict__ lbhh) {
    int t = threadIdx.x;
    if (t < D) {
        float gi = lbih[t]         + lbhh[t];
        float gg = lbih[2 * D + t] + lbhh[2 * D + t];
        float go = lbih[3 * D + t] + lbhh[3 * D + t];
        float cl = sigm(gi) * tanhf(gg);
        g_q[t] = sigm(go) * tanhf(cl);
    }
    if (t < BG) g_asum[t] = 0.f;
    for (int i = t; i < BG * D; i += blockDim.x) g_rpool[i] = 0.f;
}

// e[n] = dot(h[n], q); a = exp(e) (no max-shift: ratio identical, |e| small)
__global__ void k_dote(const int* __restrict__ batch) {
    int lane = threadIdx.x & 31;
    int warp = threadIdx.x >> 5;
    int n = blockIdx.x * 8 + warp;
    if (n >= N_NODES) return;
    float v = g_h[n * D + lane] * g_q[lane] + g_h[n * D + 32 + lane] * g_q[32 + lane];
#pragma unroll
    for (int o = 16; o > 0; o >>= 1) v += __shfl_down_sync(0xFFFFFFFFu, v, o);
    if (lane == 0) {
        float a = expf(v);
        g_a[n] = a;
        atomicAdd(&g_asum[batch[n]], a);
    }
}

__global__ void k_pool(const int* __restrict__ batch) {
    int idx = blockIdx.x * blockDim.x + threadIdx.x;
    if (idx >= N_NODES * D) return;
    int n = idx >> 6, f = idx & 63;
    int g = batch[n];
    float w = g_a[n] / g_asum[g];
    atomicAdd(&g_rpool[g * D + f], w * g_h[idx]);
}

__global__ void k_out(const float* __restrict__ Wout,
                      const float* __restrict__ bout,
                      float* __restrict__ out) {
    int t = threadIdx.x;
    if (t >= BG * 2) return;
    int b = t >> 1, c = t & 1;
    float acc = bout[c];
#pragma unroll 8
    for (int j = 0; j < D; j++) {
        acc += g_q[j] * Wout[j * 2 + c];
        acc += g_rpool[b * D + j] * Wout[(D + j) * 2 + c];
    }
    out[b * 2 + c] = acc;
}

// ---------------- launch ----------------

extern "C" void kernel_launch(void* const* d_in, const int* in_sizes, int n_in,
                              void* d_out, int out_size) {
    const float* x      = (const float*)d_in[0];
    const float* ea     = (const float*)d_in[1];
    const int*   ei     = (const int*)d_in[2];
    const int*   batch  = (const int*)d_in[3];
    const float* W0     = (const float*)d_in[4];
    const float* b0     = (const float*)d_in[5];
    const float* We1    = (const float*)d_in[6];
    const float* be1    = (const float*)d_in[7];
    const float* We2    = (const float*)d_in[8];
    const float* be2    = (const float*)d_in[9];
    const float* root   = (const float*)d_in[10];
    const float* conv_b = (const float*)d_in[11];
    const float* Wih    = (const float*)d_in[12];
    const float* Whh    = (const float*)d_in[13];
    const float* bih    = (const float*)d_in[14];
    const float* bhh    = (const float*)d_in[15];
    const float* lbih   = (const float*)d_in[18];
    const float* lbhh   = (const float*)d_in[19];
    const float* Wout   = (const float*)d_in[20];
    const float* bout   = (const float*)d_in[21];
    float* out = (float*)d_out;
    (void)in_sizes; (void)n_in; (void)out_size;

    const int TGEMM_SMEM = (128 * 72 + 64 * 72 + 64 * 136) * (int)sizeof(__half); // 45056
    cudaFuncSetAttribute(k_t_gemm, cudaFuncAttributeMaxDynamicSharedMemorySize, TGEMM_SMEM);

    dim3 tgrid(33, N_NODES / 256);   // 33*128 = 4224 >= 4160 cols; 528 blocks

    // launch index 3 (ncu capture slot) = first k_msg
    k_prep<<<2176, 256>>>(We2, be2, Wih, Whh);                      // 0
    k_init<<<(N_NODES * D + N_EDGES * D) / 256, 256>>>(x, W0, b0, ea, We1, be1, ei); // 1
    k_t_gemm<<<tgrid, 256, TGEMM_SMEM>>>();                         // 2
    k_msg<<<N_EDGES / 16, 256>>>(ei);                               // 3  <- profiled
    k_node_update<<<N_NODES / 16, 256>>>(root, conv_b, bih, bhh);   // 4

    for (int it = 1; it < 6; it++) {
        k_t_gemm<<<tgrid, 256, TGEMM_SMEM>>>();
        k_msg<<<N_EDGES / 16, 256>>>(ei);
        k_node_update<<<N_NODES / 16, 256>>>(root, conv_b, bih, bhh);
    }

    k_s2s_init<<<1, 256>>>(lbih, lbhh);
    k_dote<<<N_NODES / 8, 256>>>(batch);
    k_pool<<<(N_NODES * D) / 256, 256>>>(batch);
    k_out<<<1, 64>>>(Wout, bout, out);
}